// round 12
// baseline (speedup 1.0000x reference)
#include <cuda_runtime.h>
#include <cuda_bf16.h>
#include <cuda_fp16.h>
#include <cstdint>

#define F    256
#define VLEN 512
#define H    4
#define D    64
#define BB   8
#define NC   8

typedef __nv_bfloat16 bf16;
typedef __nv_bfloat162 bf162;

// ---------------- static device scratch ----------------
__device__ bf16   g_code2[(size_t)NC * VLEN * F];
__device__ bf16   g_tex2 [(size_t)BB * VLEN * F];
__device__ bf16   g_q[(size_t)BB * VLEN * F];
__device__ bf16   g_k[(size_t)NC * VLEN * F];
__device__ __half g_v[(size_t)NC * VLEN * F];
__device__ bf16   g_ctx[(size_t)BB * NC * VLEN * F];
__device__ float  g_x  [(size_t)BB * NC * VLEN * F];
__device__ bf16   g_w[6][F * F];

// ---------------- helpers (defined before all uses) ----------------
__device__ __forceinline__ unsigned h2_as_u32(__half2 h) {
    return *(unsigned*)&h;
}
__device__ __forceinline__ __half2 u32_as_h2(unsigned u) {
    return *(__half2*)&u;
}
__device__ __forceinline__ uint32_t smem_u32(const void* p) {
    return (uint32_t)__cvta_generic_to_shared(p);
}
__device__ __forceinline__ void mma_bf16(float (&d)[4], const unsigned (&a)[4],
                                         const unsigned b0, const unsigned b1) {
    asm volatile(
        "mma.sync.aligned.m16n8k16.row.col.f32.bf16.bf16.f32 "
        "{%0,%1,%2,%3}, {%4,%5,%6,%7}, {%8,%9}, {%0,%1,%2,%3};\n"
        : "+f"(d[0]), "+f"(d[1]), "+f"(d[2]), "+f"(d[3])
        : "r"(a[0]), "r"(a[1]), "r"(a[2]), "r"(a[3]), "r"(b0), "r"(b1));
}
__device__ __forceinline__ void mma_f16(float (&d)[4], const unsigned (&a)[4],
                                        const unsigned b0, const unsigned b1) {
    asm volatile(
        "mma.sync.aligned.m16n8k16.row.col.f32.f16.f16.f32 "
        "{%0,%1,%2,%3}, {%4,%5,%6,%7}, {%8,%9}, {%0,%1,%2,%3};\n"
        : "+f"(d[0]), "+f"(d[1]), "+f"(d[2]), "+f"(d[3])
        : "r"(a[0]), "r"(a[1]), "r"(a[2]), "r"(a[3]), "r"(b0), "r"(b1));
}
__device__ __forceinline__ void ldsm_x4(unsigned &r0, unsigned &r1,
                                        unsigned &r2, unsigned &r3, const void* p) {
    unsigned a = smem_u32(p);
    asm volatile("ldmatrix.sync.aligned.m8n8.x4.shared.b16 {%0,%1,%2,%3}, [%4];"
                 : "=r"(r0), "=r"(r1), "=r"(r2), "=r"(r3) : "r"(a));
}
__device__ __forceinline__ void ldsm_x4t(unsigned &r0, unsigned &r1,
                                         unsigned &r2, unsigned &r3, const void* p) {
    unsigned a = smem_u32(p);
    asm volatile("ldmatrix.sync.aligned.m8n8.x4.trans.shared.b16 {%0,%1,%2,%3}, [%4];"
                 : "=r"(r0), "=r"(r1), "=r"(r2), "=r"(r3) : "r"(a));
}
__device__ __forceinline__ void cp16(void* s, const void* g) {
    unsigned sa = smem_u32(s);
    asm volatile("cp.async.cg.shared.global [%0], [%1], 16;\n" :: "r"(sa), "l"(g));
}
__device__ __forceinline__ void cp_commit() { asm volatile("cp.async.commit_group;\n"); }
template<int N> __device__ __forceinline__ void cp_wait() {
    asm volatile("cp.async.wait_group %0;\n" :: "n"(N));
}

// ---------------- fused prep: weight cvt (1536 blocks) + LNs (8192 blocks) ----------------
__global__ __launch_bounds__(256) void prep_kernel(
    const float* __restrict__ code, const float* __restrict__ tex,
    const float* __restrict__ ln1g, const float* __restrict__ ln1b,
    const float* __restrict__ ln2g, const float* __restrict__ ln2b,
    const float* w0, const float* w1, const float* w2,
    const float* w3, const float* w4, const float* w5,
    bf16* __restrict__ wout)
{
    int bid = blockIdx.x;
    int t = threadIdx.x;
    if (bid < 1536) {
        int wi = bid >> 8;
        const float* s;
        switch (wi) {
            case 0: s = w0; break; case 1: s = w1; break; case 2: s = w2; break;
            case 3: s = w3; break; case 4: s = w4; break; default: s = w5; break;
        }
        int off = (bid & 255) * 256 + t;
        wout[(size_t)wi * F * F + off] = __float2bfloat16_rn(s[off]);
        return;
    }
    int row = bid - 1536;
    const float* x; const float* g; const float* b; bf16* y;
    if (row < NC * VLEN) { x = code; g = ln1g; b = ln1b; y = g_code2; }
    else { row -= NC * VLEN; x = tex; g = ln2g; b = ln2b; y = g_tex2; }

    __shared__ float sh[8];
    size_t base = (size_t)row * F;
    float v = x[base + t];

    float s = v;
    #pragma unroll
    for (int o = 16; o > 0; o >>= 1) s += __shfl_xor_sync(0xffffffffu, s, o);
    if ((t & 31) == 0) sh[t >> 5] = s;
    __syncthreads();
    float mean = (sh[0]+sh[1]+sh[2]+sh[3]+sh[4]+sh[5]+sh[6]+sh[7]) * (1.f / F);
    float d = v - mean;

    s = d * d;
    #pragma unroll
    for (int o = 16; o > 0; o >>= 1) s += __shfl_xor_sync(0xffffffffu, s, o);
    __syncthreads();
    if ((t & 31) == 0) sh[t >> 5] = s;
    __syncthreads();
    float var = (sh[0]+sh[1]+sh[2]+sh[3]+sh[4]+sh[5]+sh[6]+sh[7]) * (1.f / F);

    y[base + t] = __float2bfloat16_rn(d * rsqrtf(var + 1e-6f) * g[t] + b[t]);
}

// ======== wide-GEMM blocks: BM=64, BN=256, 256 threads, 2 CTAs/SM ========
// Resident A tile: 64 rows x 528 B. Weight streamed 3-stage (256 rows x 80 B).
#define RES_BYTES 33792               // 64 * 528
#define WB_STAGE  20480               // 256 * 80
#define QW_SMEM   (RES_BYTES + 3 * WB_STAGE)           // 95232
#define MG_SMEM   (RES_BYTES + 3 * WB_STAGE + 2048)    // 97280

// ---------------- QKV ----------------
__global__ __launch_bounds__(256, 2) void qkv_wide(
    const bf16* __restrict__ tex2, const bf16* __restrict__ code2,
    const bf16* __restrict__ wq, const bf16* __restrict__ wk, const bf16* __restrict__ wv,
    const float* __restrict__ bq, const float* __restrict__ bk, const float* __restrict__ bv,
    bf16* __restrict__ qo, bf16* __restrict__ ko, __half* __restrict__ vo)
{
    extern __shared__ char sm[];
    char* sRes = sm;
    char* sW   = sm + RES_BYTES;

    int z = blockIdx.y;
    const bf16* A = (z == 0) ? tex2 : code2;
    const bf16* W = (z == 0) ? wq : (z == 1) ? wk : wv;
    const float* bias = (z == 0) ? bq : (z == 1) ? bk : bv;

    int tid = threadIdx.x, wid = tid >> 5, lane = tid & 31;
    int g8 = lane >> 3, r8 = lane & 7, gr = lane >> 2, gc = lane & 3;
    int wm = wid >> 2, wn = wid & 3;
    int mb = wm * 32, nb = wn * 64;
    int m0 = blockIdx.x * 64;

    {
        const bf16* Ab = A + (size_t)m0 * 256;
        #pragma unroll
        for (int j = 0; j < 8; j++) {
            int idx = tid + j * 256;
            int r = idx >> 5, cs = idx & 31;
            cp16(sRes + r * 528 + cs * 16, Ab + (size_t)r * 256 + cs * 8);
        }
        cp_commit();
    }
    auto wload = [&](int ck) {
        char* sb = sW + (ck % 3) * WB_STAGE;
        int kc = ck * 32;
        #pragma unroll
        for (int j = 0; j < 4; j++) {
            int idx = tid + j * 256;
            int r = idx >> 2, cs = idx & 3;
            cp16(sb + r * 80 + cs * 16, W + (size_t)r * 256 + kc + cs * 8);
        }
        cp_commit();
    };
    wload(0); wload(1);

    float acc[2][8][4] = {};

    for (int ck = 0; ck < 8; ck++) {
        cp_wait<1>(); __syncthreads();
        if (ck + 2 < 8) wload(ck + 2);
        int ko_ = ck * 64;
        const char* sb = sW + (ck % 3) * WB_STAGE;
        #pragma unroll
        for (int s = 0; s < 2; s++) {
            unsigned af[2][4];
            #pragma unroll
            for (int mt = 0; mt < 2; mt++) {
                int row = mb + mt * 16 + (g8 & 1) * 8 + r8;
                ldsm_x4(af[mt][0], af[mt][1], af[mt][2], af[mt][3],
                        sRes + row * 528 + ko_ + s * 32 + (g8 >> 1) * 16);
            }
            #pragma unroll
            for (int np = 0; np < 4; np++) {
                int row = nb + np * 16 + (g8 >> 1) * 8 + r8;
                unsigned b0, b1, b2, b3;
                ldsm_x4(b0, b1, b2, b3, sb + row * 80 + s * 32 + (g8 & 1) * 16);
                mma_bf16(acc[0][np * 2],     af[0], b0, b1);
                mma_bf16(acc[1][np * 2],     af[1], b0, b1);
                mma_bf16(acc[0][np * 2 + 1], af[0], b2, b3);
                mma_bf16(acc[1][np * 2 + 1], af[1], b2, b3);
            }
        }
    }

    #pragma unroll
    for (int mt = 0; mt < 2; mt++) {
        #pragma unroll
        for (int hf = 0; hf < 2; hf++) {
            int rg = m0 + mb + mt * 16 + gr + hf * 8;
            size_t rb = (size_t)rg * 256;
            #pragma unroll
            for (int nt = 0; nt < 8; nt++) {
                int c = nb + nt * 8 + 2 * gc;
                float v0 = acc[mt][nt][hf * 2]     + bias[c];
                float v1 = acc[mt][nt][hf * 2 + 1] + bias[c + 1];
                if (z == 2) {
                    *(__half2*)(vo + rb + c) = __floats2half2_rn(v0, v1);
                } else {
                    bf162 o = { __float2bfloat16_rn(v0), __float2bfloat16_rn(v1) };
                    bf16* C = (z == 0) ? qo : ko;
                    *(bf162*)(C + rb + c) = o;
                }
            }
        }
    }
}

// ---------------- mega: O-proj + residual + LN + MLP1 + MLP2 ----------------
__global__ __launch_bounds__(256, 2) void mega_oln_mlp(
    const bf16* __restrict__ ctx,
    const bf16* __restrict__ wo, const bf16* __restrict__ w1, const bf16* __restrict__ w2,
    const float* __restrict__ bo, const float* __restrict__ b1, const float* __restrict__ b2,
    const float* __restrict__ tex, const float* __restrict__ ffg, const float* __restrict__ ffb,
    float* __restrict__ X, float* __restrict__ out)
{
    extern __shared__ char sm[];
    char* sRes = sm;
    char* sW   = sm + RES_BYTES;
    float* sredS = (float*)(sm + RES_BYTES + 3 * WB_STAGE);   // [64][4]
    float* sredQ = sredS + 256;                               // [64][4]

    int tid = threadIdx.x, wid = tid >> 5, lane = tid & 31;
    int g8 = lane >> 3, r8 = lane & 7, gr = lane >> 2, gc = lane & 3;
    int wm = wid >> 2, wn = wid & 3;
    int mb = wm * 32, nb = wn * 64;
    int m0 = blockIdx.x * 64;

    {
        const bf16* Ab = ctx + (size_t)m0 * 256;
        #pragma unroll
        for (int j = 0; j < 8; j++) {
            int idx = tid + j * 256;
            int r = idx >> 5, cs = idx & 31;
            cp16(sRes + r * 528 + cs * 16, Ab + (size_t)r * 256 + cs * 8);
        }
        cp_commit();
    }
    const bf16* Ws[3] = { wo, w1, w2 };
    auto wload = [&](int ck) {
        const bf16* W = Ws[ck >> 3];
        char* sb = sW + (ck % 3) * WB_STAGE;
        int kc = (ck & 7) * 32;
        #pragma unroll
        for (int j = 0; j < 4; j++) {
            int idx = tid + j * 256;
            int r = idx >> 2, cs = idx & 3;
            cp16(sb + r * 80 + cs * 16, W + (size_t)r * 256 + kc + cs * 8);
        }
        cp_commit();
    };
    wload(0); wload(1);

    float acc[2][8][4] = {};

    for (int ck = 0; ck < 24; ck++) {
        cp_wait<1>(); __syncthreads();
        if (ck + 2 < 24) wload(ck + 2);
        int ko_ = (ck & 7) * 64;
        const char* sb = sW + (ck % 3) * WB_STAGE;
        #pragma unroll
        for (int s = 0; s < 2; s++) {
            unsigned af[2][4];
            #pragma unroll
            for (int mt = 0; mt < 2; mt++) {
                int row = mb + mt * 16 + (g8 & 1) * 8 + r8;
                ldsm_x4(af[mt][0], af[mt][1], af[mt][2], af[mt][3],
                        sRes + row * 528 + ko_ + s * 32 + (g8 >> 1) * 16);
            }
            #pragma unroll
            for (int np = 0; np < 4; np++) {
                int row = nb + np * 16 + (g8 >> 1) * 8 + r8;
                unsigned b0, b1_, b2_, b3;
                ldsm_x4(b0, b1_, b2_, b3, sb + row * 80 + s * 32 + (g8 & 1) * 16);
                mma_bf16(acc[0][np * 2],     af[0], b0, b1_);
                mma_bf16(acc[1][np * 2],     af[1], b0, b1_);
                mma_bf16(acc[0][np * 2 + 1], af[0], b2_, b3);
                mma_bf16(acc[1][np * 2 + 1], af[1], b2_, b3);
            }
        }

        if (ck == 7) {
            // ---- epilogue A: x = acc + bo + tex ; write x ; LN -> yn into sRes ----
            float sS[2][2] = {}, sQ2[2][2] = {};
            #pragma unroll
            for (int mt = 0; mt < 2; mt++) {
                #pragma unroll
                for (int hf = 0; hf < 2; hf++) {
                    int rg = m0 + mb + mt * 16 + gr + hf * 8;
                    size_t rb = (size_t)rg * 256;
                    size_t tr = (size_t)(((rg >> 12) << 9) + (rg & 511)) * F;
                    #pragma unroll
                    for (int nt = 0; nt < 8; nt++) {
                        int c = nb + nt * 8 + 2 * gc;
                        float x0 = acc[mt][nt][hf * 2]     + bo[c]     + tex[tr + c];
                        float x1 = acc[mt][nt][hf * 2 + 1] + bo[c + 1] + tex[tr + c + 1];
                        acc[mt][nt][hf * 2] = x0; acc[mt][nt][hf * 2 + 1] = x1;
                        float2 o = { x0, x1 };
                        *(float2*)(X + rb + c) = o;
                        sS[mt][hf]  += x0 + x1;
                        sQ2[mt][hf] += x0 * x0 + x1 * x1;
                    }
                }
            }
            #pragma unroll
            for (int mt = 0; mt < 2; mt++)
                #pragma unroll
                for (int hf = 0; hf < 2; hf++) {
                    float a = sS[mt][hf], q = sQ2[mt][hf];
                    a += __shfl_xor_sync(0xffffffffu, a, 1);
                    a += __shfl_xor_sync(0xffffffffu, a, 2);
                    q += __shfl_xor_sync(0xffffffffu, q, 1);
                    q += __shfl_xor_sync(0xffffffffu, q, 2);
                    sS[mt][hf] = a; sQ2[mt][hf] = q;
                }
            if (gc == 0) {
                #pragma unroll
                for (int mt = 0; mt < 2; mt++)
                    #pragma unroll
                    for (int hf = 0; hf < 2; hf++) {
                        int rl = mb + mt * 16 + gr + hf * 8;
                        sredS[rl * 4 + wn] = sS[mt][hf];
                        sredQ[rl * 4 + wn] = sQ2[mt][hf];
                    }
            }
            __syncthreads();   // all mma(7) done -> sRes rewrite safe; sred visible
            #pragma unroll
            for (int mt = 0; mt < 2; mt++) {
                #pragma unroll
                for (int hf = 0; hf < 2; hf++) {
                    int rl = mb + mt * 16 + gr + hf * 8;
                    const float* ps = sredS + rl * 4;
                    const float* pq = sredQ + rl * 4;
                    float S = ps[0] + ps[1] + ps[2] + ps[3];
                    float Q = pq[0] + pq[1] + pq[2] + pq[3];
                    float mu = S * (1.f / 256.f);
                    float var = Q * (1.f / 256.f) - mu * mu;
                    float rstd = rsqrtf(var + 1e-6f);
                    #pragma unroll
                    for (int nt = 0; nt < 8; nt++) {
                        int c = nb + nt * 8 + 2 * gc;
                        float y0 = (acc[mt][nt][hf * 2]     - mu) * rstd * ffg[c]     + ffb[c];
                        float y1 = (acc[mt][nt][hf * 2 + 1] - mu) * rstd * ffg[c + 1] + ffb[c + 1];
                        bf162 o = { __float2bfloat16_rn(y0), __float2bfloat16_rn(y1) };
                        *(bf162*)(sRes + rl * 528 + c * 2) = o;
                        acc[mt][nt][hf * 2] = 0.f; acc[mt][nt][hf * 2 + 1] = 0.f;
                    }
                }
            }
            __syncthreads();
        } else if (ck == 15) {
            // ---- epilogue B: h1 = relu(acc + b1) -> sRes ----
            __syncthreads();   // all warps done reading yn
            #pragma unroll
            for (int mt = 0; mt < 2; mt++) {
                #pragma unroll
                for (int hf = 0; hf < 2; hf++) {
                    int rl = mb + mt * 16 + gr + hf * 8;
                    #pragma unroll
                    for (int nt = 0; nt < 8; nt++) {
                        int c = nb + nt * 8 + 2 * gc;
                        float h0 = fmaxf(acc[mt][nt][hf * 2]     + b1[c],     0.f);
                        float h1v = fmaxf(acc[mt][nt][hf * 2 + 1] + b1[c + 1], 0.f);
                        bf162 o = { __float2bfloat16_rn(h0), __float2bfloat16_rn(h1v) };
                        *(bf162*)(sRes + rl * 528 + c * 2) = o;
                        acc[mt][nt][hf * 2] = 0.f; acc[mt][nt][hf * 2 + 1] = 0.f;
                    }
                }
            }
            __syncthreads();
        }
    }

    // ---- epilogue C: out = acc + b2 + x ----
    #pragma unroll
    for (int mt = 0; mt < 2; mt++) {
        #pragma unroll
        for (int hf = 0; hf < 2; hf++) {
            int rg = m0 + mb + mt * 16 + gr + hf * 8;
            size_t rb = (size_t)rg * 256;
            #pragma unroll
            for (int nt = 0; nt < 8; nt++) {
                int c = nb + nt * 8 + 2 * gc;
                float o0 = acc[mt][nt][hf * 2]     + b2[c]     + X[rb + c];
                float o1 = acc[mt][nt][hf * 2 + 1] + b2[c + 1] + X[rb + c + 1];
                float2 o = { o0, o1 };
                *(float2*)(out + rb + c) = o;
            }
        }
    }
}

// ---------------- persistent fused attention (register-P, 2 barriers/tile) ----------------
#define A_SMEM 232448

__global__ __launch_bounds__(512, 1) void attn_fused(
    const bf16* __restrict__ qg, const bf16* __restrict__ kg,
    const __half* __restrict__ vg, bf16* __restrict__ og)
{
    extern __shared__ char smc[];
    bf16* sQ = (bf16*)smc;                    // stride 144 B
    bf16* sK = (bf16*)(smc + 9216);           // stride 144 B
    __half* sV = (__half*)(smc + 82944);      // stride 144 B
    char* sStage = smc + 156672;              // 8 x (64 rows x 144 B), f16
    float* sred = (float*)(smc + 230400);     // [64][8]

    int tid = threadIdx.x;
    int wid = tid >> 5, lane = tid & 31;
    int g8 = lane >> 3, r8 = lane & 7;
    int gr = lane >> 2, gc = lane & 3;

    int nh = blockIdx.y;
    int n = nh >> 2, h = nh & 3;
    int grp = blockIdx.x;

    const bf16*   K = kg + ((size_t)(n * VLEN)) * F + h * D;
    const __half* V = vg + ((size_t)(n * VLEN)) * F + h * D;

    int qr = tid >> 3, qc = (tid & 7) << 3;

    {
        int idx0 = grp * 16;
        int b0 = idx0 >> 3, q0 = idx0 & 7;
        const bf16* Q = qg + ((size_t)(b0 * VLEN + q0 * 64)) * F + h * D;
        cp16(sQ + qr * 72 + qc, Q + (size_t)qr * F + qc);
        #pragma unroll
        for (int j = 0; j < 8; j++) {
            int idx = tid + j * 512;
            int r = idx >> 3, c = (idx & 7) << 3;
            cp16(sK + r * 72 + c, K + (size_t)r * F + c);
            cp16(sV + r * 72 + c, V + (size_t)r * F + c);
        }
        cp_commit();
        cp_wait<0>();
        __syncthreads();
    }

    int wm = wid >> 3, wn = wid & 7;       // 2(m) x 8(k-split)
    const float CEXP = 0.18033688f;        // 0.125 * log2(e)

    int rr = wid * 4 + (lane >> 3);
    int rc = (lane & 7) * 8;

    for (int t = 0; t < 16; t++) {
        int idx = grp * 16 + t;
        int b = idx >> 3, qt = idx & 7;
        bf16* O = og + ((size_t)((b * NC + n) * VLEN + qt * 64)) * F + h * D;

        float acc[2][8][4] = {};
        #pragma unroll
        for (int s = 0; s < 4; s++) {
            unsigned af[2][4];
            #pragma unroll
            for (int mt = 0; mt < 2; mt++) {
                int row = wm * 32 + mt * 16 + (g8 & 1) * 8 + r8;
                ldsm_x4(af[mt][0], af[mt][1], af[mt][2], af[mt][3],
                        (const char*)sQ + row * 144 + s * 32 + (g8 >> 1) * 16);
            }
            #pragma unroll
            for (int np = 0; np < 4; np++) {
                int row = wn * 64 + np * 16 + (g8 >> 1) * 8 + r8;
                unsigned b0, b1, b2, b3;
                ldsm_x4(b0, b1, b2, b3,
                        (const char*)sK + row * 144 + s * 32 + (g8 & 1) * 16);
                mma_bf16(acc[0][np * 2],     af[0], b0, b1);
                mma_bf16(acc[1][np * 2],     af[1], b0, b1);
                mma_bf16(acc[0][np * 2 + 1], af[0], b2, b3);
                mma_bf16(acc[1][np * 2 + 1], af[1], b2, b3);
            }
        }

        unsigned ph[2][8][2];
        float rsum[2][2] = {};
        #pragma unroll
        for (int mt = 0; mt < 2; mt++)
            #pragma unroll
            for (int nt = 0; nt < 8; nt++) {
                __half2 p0 = h2exp2(__floats2half2_rn(acc[mt][nt][0] * CEXP,
                                                      acc[mt][nt][1] * CEXP));
                __half2 p1 = h2exp2(__floats2half2_rn(acc[mt][nt][2] * CEXP,
                                                      acc[mt][nt][3] * CEXP));
                ph[mt][nt][0] = h2_as_u32(p0);
                ph[mt][nt][1] = h2_as_u32(p1);
                float2 f0 = __half22float2(p0);
                float2 f1 = __half22float2(p1);
                rsum[mt][0] += f0.x + f0.y;
                rsum[mt][1] += f1.x + f1.y;
            }
        #pragma unroll
        for (int mt = 0; mt < 2; mt++)
            #pragma unroll
            for (int hf = 0; hf < 2; hf++) {
                float v = rsum[mt][hf];
                v += __shfl_xor_sync(0xffffffffu, v, 1);
                v += __shfl_xor_sync(0xffffffffu, v, 2);
                rsum[mt][hf] = v;
            }
        if (gc == 0) {
            #pragma unroll
            for (int mt = 0; mt < 2; mt++)
                #pragma unroll
                for (int hf = 0; hf < 2; hf++)
                    sred[(wm * 32 + mt * 16 + gr + hf * 8) * 8 + wn] = rsum[mt][hf];
        }

        float oacc[2][8][4] = {};
        #pragma unroll
        for (int s = 0; s < 4; s++) {
            unsigned a0[4] = { ph[0][2*s][0], ph[0][2*s][1],
                               ph[0][2*s+1][0], ph[0][2*s+1][1] };
            unsigned a1[4] = { ph[1][2*s][0], ph[1][2*s][1],
                               ph[1][2*s+1][0], ph[1][2*s+1][1] };
            #pragma unroll
            for (int nc = 0; nc < 4; nc++) {
                int row = wn * 64 + s * 16 + (g8 & 1) * 8 + r8;
                unsigned b0, b1, b2, b3;
                ldsm_x4t(b0, b1, b2, b3,
                         (const char*)sV + row * 144 + nc * 32 + (g8 >> 1) * 16);
                mma_f16(oacc[0][nc * 2],     a0, b0, b1);
                mma_f16(oacc[0][nc * 2 + 1], a0, b2, b3);
                mma_f16(oacc[1][nc * 2],     a1, b0, b1);
                mma_f16(oacc[1][nc * 2 + 1], a1, b2, b3);
            }
        }

        {
            char* st = sStage + wn * 9216;
            #pragma unroll
            for (int mt = 0; mt < 2; mt++)
                #pragma unroll
                for (int hf = 0; hf < 2; hf++) {
                    int row = wm * 32 + mt * 16 + gr + hf * 8;
                    #pragma unroll
                    for (int nt = 0; nt < 8; nt++) {
                        int c = nt * 8 + 2 * gc;
                        *(__half2*)(st + row * 144 + c * 2) =
                            __floats2half2_rn(oacc[mt][nt][hf * 2],
                                              oacc[mt][nt][hf * 2 + 1]);
                    }
                }
        }
        __syncthreads();   // B: sQ reads done; partials + sred visible

        if (t + 1 < 16) {
            int idx2 = grp * 16 + t + 1;
            int b2 = idx2 >> 3, q2 = idx2 & 7;
            const bf16* Qn = qg + ((size_t)(b2 * VLEN + q2 * 64)) * F + h * D;
            cp16(sQ + qr * 72 + qc, Qn + (size_t)qr * F + qc);
            cp_commit();
        }

        {
            const float* pr = sred + rr * 8;
            float inv = 1.f / (pr[0] + pr[1] + pr[2] + pr[3] +
                               pr[4] + pr[5] + pr[6] + pr[7]);
            float s0 = 0, s1 = 0, s2 = 0, s3 = 0, s4 = 0, s5 = 0, s6 = 0, s7 = 0;
            #pragma unroll
            for (int cp = 0; cp < 8; cp++) {
                uint4 v = *(const uint4*)(sStage + cp * 9216 + rr * 144 + rc * 2);
                float2 f0 = __half22float2(u32_as_h2(v.x));
                float2 f1 = __half22float2(u32_as_h2(v.y));
                float2 f2 = __half22float2(u32_as_h2(v.z));
                float2 f3 = __half22float2(u32_as_h2(v.w));
                s0 += f0.x; s1 += f0.y; s2 += f1.x; s3 += f1.y;
                s4 += f2.x; s5 += f2.y; s6 += f3.x; s7 += f3.y;
            }
            bf162 o0 = { __float2bfloat16_rn(s0 * inv), __float2bfloat16_rn(s1 * inv) };
            bf162 o1 = { __float2bfloat16_rn(s2 * inv), __float2bfloat16_rn(s3 * inv) };
            bf162 o2 = { __float2bfloat16_rn(s4 * inv), __float2bfloat16_rn(s5 * inv) };
            bf162 o3 = { __float2bfloat16_rn(s6 * inv), __float2bfloat16_rn(s7 * inv) };
            uint4 ov;
            ov.x = *(unsigned*)&o0; ov.y = *(unsigned*)&o1;
            ov.z = *(unsigned*)&o2; ov.w = *(unsigned*)&o3;
            *(uint4*)(O + (size_t)rr * F + rc) = ov;
        }

        cp_wait<0>();
        __syncthreads();   // C: reduce reads done; next Q arrived
    }
}

// ---------------- launch ----------------
extern "C" void kernel_launch(void* const* d_in, const int* /*in_sizes*/, int /*n_in*/,
                              void* d_out, int /*out_size*/)
{
    const float* code = (const float*)d_in[0];
    const float* tex  = (const float*)d_in[1];
    const float* Wq   = (const float*)d_in[2];  const float* bq = (const float*)d_in[3];
    const float* Wk   = (const float*)d_in[4];  const float* bk = (const float*)d_in[5];
    const float* Wv   = (const float*)d_in[6];  const float* bv = (const float*)d_in[7];
    const float* Wo   = (const float*)d_in[8];  const float* bo = (const float*)d_in[9];
    const float* ln1g = (const float*)d_in[10]; const float* ln1b = (const float*)d_in[11];
    const float* ln2g = (const float*)d_in[12]; const float* ln2b = (const float*)d_in[13];
    const float* ffg  = (const float*)d_in[14]; const float* ffb  = (const float*)d_in[15];
    const float* W1   = (const float*)d_in[16]; const float* b1 = (const float*)d_in[17];
    const float* W2   = (const float*)d_in[18]; const float* b2 = (const float*)d_in[19];
    float* out = (float*)d_out;

    bf16 *p_code2, *p_tex2, *p_q, *p_k, *p_ctx, *p_w;
    __half *p_v;
    float *p_x;
    cudaGetSymbolAddress((void**)&p_code2, g_code2);
    cudaGetSymbolAddress((void**)&p_tex2,  g_tex2);
    cudaGetSymbolAddress((void**)&p_q,     g_q);
    cudaGetSymbolAddress((void**)&p_k,     g_k);
    cudaGetSymbolAddress((void**)&p_v,     g_v);
    cudaGetSymbolAddress((void**)&p_ctx,   g_ctx);
    cudaGetSymbolAddress((void**)&p_x,     g_x);
    cudaGetSymbolAddress((void**)&p_w,     g_w);
    bf16* wq = p_w;             bf16* wk = p_w + 1 * F * F; bf16* wv = p_w + 2 * F * F;
    bf16* wo = p_w + 3 * F * F; bf16* w1 = p_w + 4 * F * F; bf16* w2 = p_w + 5 * F * F;

    cudaFuncSetAttribute(qkv_wide,     cudaFuncAttributeMaxDynamicSharedMemorySize, QW_SMEM);
    cudaFuncSetAttribute(mega_oln_mlp, cudaFuncAttributeMaxDynamicSharedMemorySize, MG_SMEM);
    cudaFuncSetAttribute(attn_fused,   cudaFuncAttributeMaxDynamicSharedMemorySize, A_SMEM);

    // 1) fused prep: weight cvt + both LayerNorms
    prep_kernel<<<1536 + (NC + BB) * VLEN, 256>>>(
        code, tex, ln1g, ln1b, ln2g, ln2b,
        Wq, Wk, Wv, Wo, W1, W2, p_w);

    // 2) Q/K/V projections (BM=64, 2 CTAs/SM)
    qkv_wide<<<dim3(64, 3), 256, QW_SMEM>>>(
        p_tex2, p_code2, wq, wk, wv, bq, bk, bv, p_q, p_k, p_v);

    // 3) persistent fused attention (register-P) -> ctx (bf16)
    attn_fused<<<dim3(4, 32), 512, A_SMEM>>>(p_q, p_k, p_v, p_ctx);

    // 4) O-proj + residual + LN + MLP1 + MLP2 (BM=64, 2 CTAs/SM)
    mega_oln_mlp<<<512, 256, MG_SMEM>>>(
        p_ctx, wo, w1, w2, bo, b1, b2, tex, ffg, ffb, p_x, out);
}

// round 13
// speedup vs baseline: 1.6219x; 1.6219x over previous
#include <cuda_runtime.h>
#include <cuda_bf16.h>
#include <cuda_fp16.h>
#include <cstdint>

#define F    256
#define VLEN 512
#define H    4
#define D    64
#define BB   8
#define NC   8

typedef __nv_bfloat16 bf16;
typedef __nv_bfloat162 bf162;

// ---------------- static device scratch ----------------
__device__ bf16   g_code2[(size_t)NC * VLEN * F];
__device__ bf16   g_tex2 [(size_t)BB * VLEN * F];
__device__ bf16   g_q[(size_t)BB * VLEN * F];
__device__ bf16   g_k[(size_t)NC * VLEN * F];
__device__ __half g_v[(size_t)NC * VLEN * F];
__device__ bf16   g_ctx[(size_t)BB * NC * VLEN * F];
__device__ float  g_x  [(size_t)BB * NC * VLEN * F];
__device__ bf16   g_w[6][F * F];

// ---------------- helpers ----------------
__device__ __forceinline__ unsigned h2_as_u32(__half2 h) {
    return *(unsigned*)&h;
}
__device__ __forceinline__ __half2 u32_as_h2(unsigned u) {
    return *(__half2*)&u;
}
__device__ __forceinline__ uint32_t smem_u32(const void* p) {
    return (uint32_t)__cvta_generic_to_shared(p);
}
__device__ __forceinline__ void mma_bf16(float (&d)[4], const unsigned (&a)[4],
                                         const unsigned b0, const unsigned b1) {
    asm volatile(
        "mma.sync.aligned.m16n8k16.row.col.f32.bf16.bf16.f32 "
        "{%0,%1,%2,%3}, {%4,%5,%6,%7}, {%8,%9}, {%0,%1,%2,%3};\n"
        : "+f"(d[0]), "+f"(d[1]), "+f"(d[2]), "+f"(d[3])
        : "r"(a[0]), "r"(a[1]), "r"(a[2]), "r"(a[3]), "r"(b0), "r"(b1));
}
__device__ __forceinline__ void mma_f16(float (&d)[4], const unsigned (&a)[4],
                                        const unsigned b0, const unsigned b1) {
    asm volatile(
        "mma.sync.aligned.m16n8k16.row.col.f32.f16.f16.f32 "
        "{%0,%1,%2,%3}, {%4,%5,%6,%7}, {%8,%9}, {%0,%1,%2,%3};\n"
        : "+f"(d[0]), "+f"(d[1]), "+f"(d[2]), "+f"(d[3])
        : "r"(a[0]), "r"(a[1]), "r"(a[2]), "r"(a[3]), "r"(b0), "r"(b1));
}
__device__ __forceinline__ void ldsm_x4(unsigned &r0, unsigned &r1,
                                        unsigned &r2, unsigned &r3, const void* p) {
    unsigned a = smem_u32(p);
    asm volatile("ldmatrix.sync.aligned.m8n8.x4.shared.b16 {%0,%1,%2,%3}, [%4];"
                 : "=r"(r0), "=r"(r1), "=r"(r2), "=r"(r3) : "r"(a));
}
__device__ __forceinline__ void ldsm_x4t(unsigned &r0, unsigned &r1,
                                         unsigned &r2, unsigned &r3, const void* p) {
    unsigned a = smem_u32(p);
    asm volatile("ldmatrix.sync.aligned.m8n8.x4.trans.shared.b16 {%0,%1,%2,%3}, [%4];"
                 : "=r"(r0), "=r"(r1), "=r"(r2), "=r"(r3) : "r"(a));
}
__device__ __forceinline__ void cp16(void* s, const void* g) {
    unsigned sa = smem_u32(s);
    asm volatile("cp.async.cg.shared.global [%0], [%1], 16;\n" :: "r"(sa), "l"(g));
}
__device__ __forceinline__ void cp_commit() { asm volatile("cp.async.commit_group;\n"); }
template<int N> __device__ __forceinline__ void cp_wait() {
    asm volatile("cp.async.wait_group %0;\n" :: "n"(N));
}

// ---------------- fused prep ----------------
__global__ __launch_bounds__(256) void prep_kernel(
    const float* __restrict__ code, const float* __restrict__ tex,
    const float* __restrict__ ln1g, const float* __restrict__ ln1b,
    const float* __restrict__ ln2g, const float* __restrict__ ln2b,
    const float* w0, const float* w1, const float* w2,
    const float* w3, const float* w4, const float* w5,
    bf16* __restrict__ wout)
{
    int bid = blockIdx.x;
    int t = threadIdx.x;
    if (bid < 1536) {
        int wi = bid >> 8;
        const float* s;
        switch (wi) {
            case 0: s = w0; break; case 1: s = w1; break; case 2: s = w2; break;
            case 3: s = w3; break; case 4: s = w4; break; default: s = w5; break;
        }
        int off = (bid & 255) * 256 + t;
        wout[(size_t)wi * F * F + off] = __float2bfloat16_rn(s[off]);
        return;
    }
    int row = bid - 1536;
    const float* x; const float* g; const float* b; bf16* y;
    if (row < NC * VLEN) { x = code; g = ln1g; b = ln1b; y = g_code2; }
    else { row -= NC * VLEN; x = tex; g = ln2g; b = ln2b; y = g_tex2; }

    __shared__ float sh[8];
    size_t base = (size_t)row * F;
    float v = x[base + t];

    float s = v;
    #pragma unroll
    for (int o = 16; o > 0; o >>= 1) s += __shfl_xor_sync(0xffffffffu, s, o);
    if ((t & 31) == 0) sh[t >> 5] = s;
    __syncthreads();
    float mean = (sh[0]+sh[1]+sh[2]+sh[3]+sh[4]+sh[5]+sh[6]+sh[7]) * (1.f / F);
    float d = v - mean;

    s = d * d;
    #pragma unroll
    for (int o = 16; o > 0; o >>= 1) s += __shfl_xor_sync(0xffffffffu, s, o);
    __syncthreads();
    if ((t & 31) == 0) sh[t >> 5] = s;
    __syncthreads();
    float var = (sh[0]+sh[1]+sh[2]+sh[3]+sh[4]+sh[5]+sh[6]+sh[7]) * (1.f / F);

    y[base + t] = __float2bfloat16_rn(d * rsqrtf(var + 1e-6f) * g[t] + b[t]);
}

// ======== wide-GEMM: BM=128, BN=256, 512 threads, BK=64 stages ========
// Resident A: 128 rows x 528 B. Weight stage: 256 rows x 144 B (64 bf16 cols + pad).
#define RES_BYTES 67584               // 128 * 528
#define WB_STAGE  36864               // 256 * 144
#define QW_SMEM   (RES_BYTES + 3 * WB_STAGE)           // 178176
#define MG_SMEM   (RES_BYTES + 3 * WB_STAGE + 4096)    // 182272

// ---------------- QKV ----------------
__global__ __launch_bounds__(512, 1) void qkv_wide(
    const bf16* __restrict__ tex2, const bf16* __restrict__ code2,
    const bf16* __restrict__ wq, const bf16* __restrict__ wk, const bf16* __restrict__ wv,
    const float* __restrict__ bq, const float* __restrict__ bk, const float* __restrict__ bv,
    bf16* __restrict__ qo, bf16* __restrict__ ko, __half* __restrict__ vo)
{
    extern __shared__ char sm[];
    char* sRes = sm;
    char* sW   = sm + RES_BYTES;

    int z = blockIdx.y;
    const bf16* A = (z == 0) ? tex2 : code2;
    const bf16* W = (z == 0) ? wq : (z == 1) ? wk : wv;
    const float* bias = (z == 0) ? bq : (z == 1) ? bk : bv;

    int tid = threadIdx.x, wid = tid >> 5, lane = tid & 31;
    int g8 = lane >> 3, r8 = lane & 7, gr = lane >> 2, gc = lane & 3;
    int wm = wid >> 2, wn = wid & 3;
    int mb = wm * 32, nb = wn * 64;
    int m0 = blockIdx.x * 128;

    {
        const bf16* Ab = A + (size_t)m0 * 256;
        #pragma unroll
        for (int j = 0; j < 8; j++) {
            int idx = tid + j * 512;
            int r = idx >> 5, cs = idx & 31;
            cp16(sRes + r * 528 + cs * 16, Ab + (size_t)r * 256 + cs * 8);
        }
        cp_commit();
    }
    auto wload = [&](int ck) {
        char* sb = sW + (ck % 3) * WB_STAGE;
        int kc = ck * 64;
        #pragma unroll
        for (int j = 0; j < 4; j++) {
            int idx = tid + j * 512;
            int r = idx >> 3, cs = idx & 7;
            cp16(sb + r * 144 + cs * 16, W + (size_t)r * 256 + kc + cs * 8);
        }
        cp_commit();
    };
    wload(0); wload(1);

    float acc[2][8][4] = {};

    for (int ck = 0; ck < 4; ck++) {
        cp_wait<1>(); __syncthreads();
        if (ck + 2 < 4) wload(ck + 2);
        int ko_ = ck * 128;
        const char* sb = sW + (ck % 3) * WB_STAGE;
        #pragma unroll
        for (int s = 0; s < 4; s++) {
            unsigned af[2][4];
            #pragma unroll
            for (int mt = 0; mt < 2; mt++) {
                int row = mb + mt * 16 + (g8 & 1) * 8 + r8;
                ldsm_x4(af[mt][0], af[mt][1], af[mt][2], af[mt][3],
                        sRes + row * 528 + ko_ + s * 32 + (g8 >> 1) * 16);
            }
            #pragma unroll
            for (int np = 0; np < 4; np++) {
                int row = nb + np * 16 + (g8 >> 1) * 8 + r8;
                unsigned b0, b1, b2, b3;
                ldsm_x4(b0, b1, b2, b3, sb + row * 144 + s * 32 + (g8 & 1) * 16);
                mma_bf16(acc[0][np * 2],     af[0], b0, b1);
                mma_bf16(acc[1][np * 2],     af[1], b0, b1);
                mma_bf16(acc[0][np * 2 + 1], af[0], b2, b3);
                mma_bf16(acc[1][np * 2 + 1], af[1], b2, b3);
            }
        }
    }

    #pragma unroll
    for (int mt = 0; mt < 2; mt++) {
        #pragma unroll
        for (int hf = 0; hf < 2; hf++) {
            int rg = m0 + mb + mt * 16 + gr + hf * 8;
            size_t rb = (size_t)rg * 256;
            #pragma unroll
            for (int nt = 0; nt < 8; nt++) {
                int c = nb + nt * 8 + 2 * gc;
                float v0 = acc[mt][nt][hf * 2]     + bias[c];
                float v1 = acc[mt][nt][hf * 2 + 1] + bias[c + 1];
                if (z == 2) {
                    *(__half2*)(vo + rb + c) = __floats2half2_rn(v0, v1);
                } else {
                    bf162 o = { __float2bfloat16_rn(v0), __float2bfloat16_rn(v1) };
                    bf16* C = (z == 0) ? qo : ko;
                    *(bf162*)(C + rb + c) = o;
                }
            }
        }
    }
}

// ---------------- mega: O-proj + residual + LN + MLP1 + MLP2 (BK=64) ----------------
__global__ __launch_bounds__(512, 1) void mega_oln_mlp(
    const bf16* __restrict__ ctx,
    const bf16* __restrict__ wo, const bf16* __restrict__ w1, const bf16* __restrict__ w2,
    const float* __restrict__ bo, const float* __restrict__ b1, const float* __restrict__ b2,
    const float* __restrict__ tex, const float* __restrict__ ffg, const float* __restrict__ ffb,
    float* __restrict__ X, float* __restrict__ out)
{
    extern __shared__ char sm[];
    char* sRes = sm;
    char* sW   = sm + RES_BYTES;
    float* sredS = (float*)(sm + RES_BYTES + 3 * WB_STAGE);   // [128][4]
    float* sredQ = sredS + 512;

    int tid = threadIdx.x, wid = tid >> 5, lane = tid & 31;
    int g8 = lane >> 3, r8 = lane & 7, gr = lane >> 2, gc = lane & 3;
    int wm = wid >> 2, wn = wid & 3;
    int mb = wm * 32, nb = wn * 64;
    int m0 = blockIdx.x * 128;

    {
        const bf16* Ab = ctx + (size_t)m0 * 256;
        #pragma unroll
        for (int j = 0; j < 8; j++) {
            int idx = tid + j * 512;
            int r = idx >> 5, cs = idx & 31;
            cp16(sRes + r * 528 + cs * 16, Ab + (size_t)r * 256 + cs * 8);
        }
        cp_commit();
    }
    const bf16* Ws[3] = { wo, w1, w2 };
    auto wload = [&](int ck) {
        const bf16* W = Ws[ck >> 2];
        char* sb = sW + (ck % 3) * WB_STAGE;
        int kc = (ck & 3) * 64;
        #pragma unroll
        for (int j = 0; j < 4; j++) {
            int idx = tid + j * 512;
            int r = idx >> 3, cs = idx & 7;
            cp16(sb + r * 144 + cs * 16, W + (size_t)r * 256 + kc + cs * 8);
        }
        cp_commit();
    };
    wload(0); wload(1);

    float acc[2][8][4] = {};

    for (int ck = 0; ck < 12; ck++) {
        cp_wait<1>(); __syncthreads();
        if (ck + 2 < 12) wload(ck + 2);
        int ko_ = (ck & 3) * 128;
        const char* sb = sW + (ck % 3) * WB_STAGE;
        #pragma unroll
        for (int s = 0; s < 4; s++) {
            unsigned af[2][4];
            #pragma unroll
            for (int mt = 0; mt < 2; mt++) {
                int row = mb + mt * 16 + (g8 & 1) * 8 + r8;
                ldsm_x4(af[mt][0], af[mt][1], af[mt][2], af[mt][3],
                        sRes + row * 528 + ko_ + s * 32 + (g8 >> 1) * 16);
            }
            #pragma unroll
            for (int np = 0; np < 4; np++) {
                int row = nb + np * 16 + (g8 >> 1) * 8 + r8;
                unsigned b0, b1_, b2_, b3;
                ldsm_x4(b0, b1_, b2_, b3, sb + row * 144 + s * 32 + (g8 & 1) * 16);
                mma_bf16(acc[0][np * 2],     af[0], b0, b1_);
                mma_bf16(acc[1][np * 2],     af[1], b0, b1_);
                mma_bf16(acc[0][np * 2 + 1], af[0], b2_, b3);
                mma_bf16(acc[1][np * 2 + 1], af[1], b2_, b3);
            }
        }

        if (ck == 3) {
            // ---- epilogue A: x = acc + bo + tex; write x; LN -> yn into sRes ----
            float sS[2][2] = {}, sQ2[2][2] = {};
            #pragma unroll
            for (int mt = 0; mt < 2; mt++) {
                #pragma unroll
                for (int hf = 0; hf < 2; hf++) {
                    int rg = m0 + mb + mt * 16 + gr + hf * 8;
                    size_t rb = (size_t)rg * 256;
                    size_t tr = (size_t)(((rg >> 12) << 9) + (rg & 511)) * F;
                    #pragma unroll
                    for (int nt = 0; nt < 8; nt++) {
                        int c = nb + nt * 8 + 2 * gc;
                        float x0 = acc[mt][nt][hf * 2]     + bo[c]     + tex[tr + c];
                        float x1 = acc[mt][nt][hf * 2 + 1] + bo[c + 1] + tex[tr + c + 1];
                        acc[mt][nt][hf * 2] = x0; acc[mt][nt][hf * 2 + 1] = x1;
                        float2 o = { x0, x1 };
                        *(float2*)(X + rb + c) = o;
                        sS[mt][hf]  += x0 + x1;
                        sQ2[mt][hf] += x0 * x0 + x1 * x1;
                    }
                }
            }
            #pragma unroll
            for (int mt = 0; mt < 2; mt++)
                #pragma unroll
                for (int hf = 0; hf < 2; hf++) {
                    float a = sS[mt][hf], q = sQ2[mt][hf];
                    a += __shfl_xor_sync(0xffffffffu, a, 1);
                    a += __shfl_xor_sync(0xffffffffu, a, 2);
                    q += __shfl_xor_sync(0xffffffffu, q, 1);
                    q += __shfl_xor_sync(0xffffffffu, q, 2);
                    sS[mt][hf] = a; sQ2[mt][hf] = q;
                }
            if (gc == 0) {
                #pragma unroll
                for (int mt = 0; mt < 2; mt++)
                    #pragma unroll
                    for (int hf = 0; hf < 2; hf++) {
                        int rl = mb + mt * 16 + gr + hf * 8;
                        sredS[rl * 4 + wn] = sS[mt][hf];
                        sredQ[rl * 4 + wn] = sQ2[mt][hf];
                    }
            }
            __syncthreads();
            #pragma unroll
            for (int mt = 0; mt < 2; mt++) {
                #pragma unroll
                for (int hf = 0; hf < 2; hf++) {
                    int rl = mb + mt * 16 + gr + hf * 8;
                    const float* ps = sredS + rl * 4;
                    const float* pq = sredQ + rl * 4;
                    float S = ps[0] + ps[1] + ps[2] + ps[3];
                    float Q = pq[0] + pq[1] + pq[2] + pq[3];
                    float mu = S * (1.f / 256.f);
                    float var = Q * (1.f / 256.f) - mu * mu;
                    float rstd = rsqrtf(var + 1e-6f);
                    #pragma unroll
                    for (int nt = 0; nt < 8; nt++) {
                        int c = nb + nt * 8 + 2 * gc;
                        float y0 = (acc[mt][nt][hf * 2]     - mu) * rstd * ffg[c]     + ffb[c];
                        float y1 = (acc[mt][nt][hf * 2 + 1] - mu) * rstd * ffg[c + 1] + ffb[c + 1];
                        bf162 o = { __float2bfloat16_rn(y0), __float2bfloat16_rn(y1) };
                        *(bf162*)(sRes + rl * 528 + c * 2) = o;
                        acc[mt][nt][hf * 2] = 0.f; acc[mt][nt][hf * 2 + 1] = 0.f;
                    }
                }
            }
            __syncthreads();
        } else if (ck == 7) {
            // ---- epilogue B: h1 = relu(acc + b1) -> sRes ----
            __syncthreads();
            #pragma unroll
            for (int mt = 0; mt < 2; mt++) {
                #pragma unroll
                for (int hf = 0; hf < 2; hf++) {
                    int rl = mb + mt * 16 + gr + hf * 8;
                    #pragma unroll
                    for (int nt = 0; nt < 8; nt++) {
                        int c = nb + nt * 8 + 2 * gc;
                        float h0 = fmaxf(acc[mt][nt][hf * 2]     + b1[c],     0.f);
                        float h1v = fmaxf(acc[mt][nt][hf * 2 + 1] + b1[c + 1], 0.f);
                        bf162 o = { __float2bfloat16_rn(h0), __float2bfloat16_rn(h1v) };
                        *(bf162*)(sRes + rl * 528 + c * 2) = o;
                        acc[mt][nt][hf * 2] = 0.f; acc[mt][nt][hf * 2 + 1] = 0.f;
                    }
                }
            }
            __syncthreads();
        }
    }

    // ---- epilogue C: out = acc + b2 + x ----
    #pragma unroll
    for (int mt = 0; mt < 2; mt++) {
        #pragma unroll
        for (int hf = 0; hf < 2; hf++) {
            int rg = m0 + mb + mt * 16 + gr + hf * 8;
            size_t rb = (size_t)rg * 256;
            #pragma unroll
            for (int nt = 0; nt < 8; nt++) {
                int c = nb + nt * 8 + 2 * gc;
                float o0 = acc[mt][nt][hf * 2]     + b2[c]     + X[rb + c];
                float o1 = acc[mt][nt][hf * 2 + 1] + b2[c + 1] + X[rb + c + 1];
                float2 o = { o0, o1 };
                *(float2*)(out + rb + c) = o;
            }
        }
    }
}

// ---------------- persistent fused attention (register-P) — unchanged from R11 ----------------
#define A_SMEM 232448

__global__ __launch_bounds__(512, 1) void attn_fused(
    const bf16* __restrict__ qg, const bf16* __restrict__ kg,
    const __half* __restrict__ vg, bf16* __restrict__ og)
{
    extern __shared__ char smc[];
    bf16* sQ = (bf16*)smc;
    bf16* sK = (bf16*)(smc + 9216);
    __half* sV = (__half*)(smc + 82944);
    char* sStage = smc + 156672;
    float* sred = (float*)(smc + 230400);

    int tid = threadIdx.x;
    int wid = tid >> 5, lane = tid & 31;
    int g8 = lane >> 3, r8 = lane & 7;
    int gr = lane >> 2, gc = lane & 3;

    int nh = blockIdx.y;
    int n = nh >> 2, h = nh & 3;
    int grp = blockIdx.x;

    const bf16*   K = kg + ((size_t)(n * VLEN)) * F + h * D;
    const __half* V = vg + ((size_t)(n * VLEN)) * F + h * D;

    int qr = tid >> 3, qc = (tid & 7) << 3;

    {
        int idx0 = grp * 16;
        int b0 = idx0 >> 3, q0 = idx0 & 7;
        const bf16* Q = qg + ((size_t)(b0 * VLEN + q0 * 64)) * F + h * D;
        cp16(sQ + qr * 72 + qc, Q + (size_t)qr * F + qc);
        #pragma unroll
        for (int j = 0; j < 8; j++) {
            int idx = tid + j * 512;
            int r = idx >> 3, c = (idx & 7) << 3;
            cp16(sK + r * 72 + c, K + (size_t)r * F + c);
            cp16(sV + r * 72 + c, V + (size_t)r * F + c);
        }
        cp_commit();
        cp_wait<0>();
        __syncthreads();
    }

    int wm = wid >> 3, wn = wid & 7;
    const float CEXP = 0.18033688f;

    int rr = wid * 4 + (lane >> 3);
    int rc = (lane & 7) * 8;

    for (int t = 0; t < 16; t++) {
        int idx = grp * 16 + t;
        int b = idx >> 3, qt = idx & 7;
        bf16* O = og + ((size_t)((b * NC + n) * VLEN + qt * 64)) * F + h * D;

        float acc[2][8][4] = {};
        #pragma unroll
        for (int s = 0; s < 4; s++) {
            unsigned af[2][4];
            #pragma unroll
            for (int mt = 0; mt < 2; mt++) {
                int row = wm * 32 + mt * 16 + (g8 & 1) * 8 + r8;
                ldsm_x4(af[mt][0], af[mt][1], af[mt][2], af[mt][3],
                        (const char*)sQ + row * 144 + s * 32 + (g8 >> 1) * 16);
            }
            #pragma unroll
            for (int np = 0; np < 4; np++) {
                int row = wn * 64 + np * 16 + (g8 >> 1) * 8 + r8;
                unsigned b0, b1, b2, b3;
                ldsm_x4(b0, b1, b2, b3,
                        (const char*)sK + row * 144 + s * 32 + (g8 & 1) * 16);
                mma_bf16(acc[0][np * 2],     af[0], b0, b1);
                mma_bf16(acc[1][np * 2],     af[1], b0, b1);
                mma_bf16(acc[0][np * 2 + 1], af[0], b2, b3);
                mma_bf16(acc[1][np * 2 + 1], af[1], b2, b3);
            }
        }

        unsigned ph[2][8][2];
        float rsum[2][2] = {};
        #pragma unroll
        for (int mt = 0; mt < 2; mt++)
            #pragma unroll
            for (int nt = 0; nt < 8; nt++) {
                __half2 p0 = h2exp2(__floats2half2_rn(acc[mt][nt][0] * CEXP,
                                                      acc[mt][nt][1] * CEXP));
                __half2 p1 = h2exp2(__floats2half2_rn(acc[mt][nt][2] * CEXP,
                                                      acc[mt][nt][3] * CEXP));
                ph[mt][nt][0] = h2_as_u32(p0);
                ph[mt][nt][1] = h2_as_u32(p1);
                float2 f0 = __half22float2(p0);
                float2 f1 = __half22float2(p1);
                rsum[mt][0] += f0.x + f0.y;
                rsum[mt][1] += f1.x + f1.y;
            }
        #pragma unroll
        for (int mt = 0; mt < 2; mt++)
            #pragma unroll
            for (int hf = 0; hf < 2; hf++) {
                float v = rsum[mt][hf];
                v += __shfl_xor_sync(0xffffffffu, v, 1);
                v += __shfl_xor_sync(0xffffffffu, v, 2);
                rsum[mt][hf] = v;
            }
        if (gc == 0) {
            #pragma unroll
            for (int mt = 0; mt < 2; mt++)
                #pragma unroll
                for (int hf = 0; hf < 2; hf++)
                    sred[(wm * 32 + mt * 16 + gr + hf * 8) * 8 + wn] = rsum[mt][hf];
        }

        float oacc[2][8][4] = {};
        #pragma unroll
        for (int s = 0; s < 4; s++) {
            unsigned a0[4] = { ph[0][2*s][0], ph[0][2*s][1],
                               ph[0][2*s+1][0], ph[0][2*s+1][1] };
            unsigned a1[4] = { ph[1][2*s][0], ph[1][2*s][1],
                               ph[1][2*s+1][0], ph[1][2*s+1][1] };
            #pragma unroll
            for (int nc = 0; nc < 4; nc++) {
                int row = wn * 64 + s * 16 + (g8 & 1) * 8 + r8;
                unsigned b0, b1, b2, b3;
                ldsm_x4t(b0, b1, b2, b3,
                         (const char*)sV + row * 144 + nc * 32 + (g8 >> 1) * 16);
                mma_f16(oacc[0][nc * 2],     a0, b0, b1);
                mma_f16(oacc[0][nc * 2 + 1], a0, b2, b3);
                mma_f16(oacc[1][nc * 2],     a1, b0, b1);
                mma_f16(oacc[1][nc * 2 + 1], a1, b2, b3);
            }
        }

        {
            char* st = sStage + wn * 9216;
            #pragma unroll
            for (int mt = 0; mt < 2; mt++)
                #pragma unroll
                for (int hf = 0; hf < 2; hf++) {
                    int row = wm * 32 + mt * 16 + gr + hf * 8;
                    #pragma unroll
                    for (int nt = 0; nt < 8; nt++) {
                        int c = nt * 8 + 2 * gc;
                        *(__half2*)(st + row * 144 + c * 2) =
                            __floats2half2_rn(oacc[mt][nt][hf * 2],
                                              oacc[mt][nt][hf * 2 + 1]);
                    }
                }
        }
        __syncthreads();

        if (t + 1 < 16) {
            int idx2 = grp * 16 + t + 1;
            int b2 = idx2 >> 3, q2 = idx2 & 7;
            const bf16* Qn = qg + ((size_t)(b2 * VLEN + q2 * 64)) * F + h * D;
            cp16(sQ + qr * 72 + qc, Qn + (size_t)qr * F + qc);
            cp_commit();
        }

        {
            const float* pr = sred + rr * 8;
            float inv = 1.f / (pr[0] + pr[1] + pr[2] + pr[3] +
                               pr[4] + pr[5] + pr[6] + pr[7]);
            float s0 = 0, s1 = 0, s2 = 0, s3 = 0, s4 = 0, s5 = 0, s6 = 0, s7 = 0;
            #pragma unroll
            for (int cp = 0; cp < 8; cp++) {
                uint4 v = *(const uint4*)(sStage + cp * 9216 + rr * 144 + rc * 2);
                float2 f0 = __half22float2(u32_as_h2(v.x));
                float2 f1 = __half22float2(u32_as_h2(v.y));
                float2 f2 = __half22float2(u32_as_h2(v.z));
                float2 f3 = __half22float2(u32_as_h2(v.w));
                s0 += f0.x; s1 += f0.y; s2 += f1.x; s3 += f1.y;
                s4 += f2.x; s5 += f2.y; s6 += f3.x; s7 += f3.y;
            }
            bf162 o0 = { __float2bfloat16_rn(s0 * inv), __float2bfloat16_rn(s1 * inv) };
            bf162 o1 = { __float2bfloat16_rn(s2 * inv), __float2bfloat16_rn(s3 * inv) };
            bf162 o2 = { __float2bfloat16_rn(s4 * inv), __float2bfloat16_rn(s5 * inv) };
            bf162 o3 = { __float2bfloat16_rn(s6 * inv), __float2bfloat16_rn(s7 * inv) };
            uint4 ov;
            ov.x = *(unsigned*)&o0; ov.y = *(unsigned*)&o1;
            ov.z = *(unsigned*)&o2; ov.w = *(unsigned*)&o3;
            *(uint4*)(O + (size_t)rr * F + rc) = ov;
        }

        cp_wait<0>();
        __syncthreads();
    }
}

// ---------------- launch ----------------
extern "C" void kernel_launch(void* const* d_in, const int* /*in_sizes*/, int /*n_in*/,
                              void* d_out, int /*out_size*/)
{
    const float* code = (const float*)d_in[0];
    const float* tex  = (const float*)d_in[1];
    const float* Wq   = (const float*)d_in[2];  const float* bq = (const float*)d_in[3];
    const float* Wk   = (const float*)d_in[4];  const float* bk = (const float*)d_in[5];
    const float* Wv   = (const float*)d_in[6];  const float* bv = (const float*)d_in[7];
    const float* Wo   = (const float*)d_in[8];  const float* bo = (const float*)d_in[9];
    const float* ln1g = (const float*)d_in[10]; const float* ln1b = (const float*)d_in[11];
    const float* ln2g = (const float*)d_in[12]; const float* ln2b = (const float*)d_in[13];
    const float* ffg  = (const float*)d_in[14]; const float* ffb  = (const float*)d_in[15];
    const float* W1   = (const float*)d_in[16]; const float* b1 = (const float*)d_in[17];
    const float* W2   = (const float*)d_in[18]; const float* b2 = (const float*)d_in[19];
    float* out = (float*)d_out;

    bf16 *p_code2, *p_tex2, *p_q, *p_k, *p_ctx, *p_w;
    __half *p_v;
    float *p_x;
    cudaGetSymbolAddress((void**)&p_code2, g_code2);
    cudaGetSymbolAddress((void**)&p_tex2,  g_tex2);
    cudaGetSymbolAddress((void**)&p_q,     g_q);
    cudaGetSymbolAddress((void**)&p_k,     g_k);
    cudaGetSymbolAddress((void**)&p_v,     g_v);
    cudaGetSymbolAddress((void**)&p_ctx,   g_ctx);
    cudaGetSymbolAddress((void**)&p_x,     g_x);
    cudaGetSymbolAddress((void**)&p_w,     g_w);
    bf16* wq = p_w;             bf16* wk = p_w + 1 * F * F; bf16* wv = p_w + 2 * F * F;
    bf16* wo = p_w + 3 * F * F; bf16* w1 = p_w + 4 * F * F; bf16* w2 = p_w + 5 * F * F;

    cudaFuncSetAttribute(qkv_wide,     cudaFuncAttributeMaxDynamicSharedMemorySize, QW_SMEM);
    cudaFuncSetAttribute(mega_oln_mlp, cudaFuncAttributeMaxDynamicSharedMemorySize, MG_SMEM);
    cudaFuncSetAttribute(attn_fused,   cudaFuncAttributeMaxDynamicSharedMemorySize, A_SMEM);

    // 1) fused prep
    prep_kernel<<<1536 + (NC + BB) * VLEN, 256>>>(
        code, tex, ln1g, ln1b, ln2g, ln2b,
        Wq, Wk, Wv, Wo, W1, W2, p_w);

    // 2) Q/K/V projections (BM=128, BK=64)
    qkv_wide<<<dim3(32, 3), 512, QW_SMEM>>>(
        p_tex2, p_code2, wq, wk, wv, bq, bk, bv, p_q, p_k, p_v);

    // 3) persistent fused attention
    attn_fused<<<dim3(4, 32), 512, A_SMEM>>>(p_q, p_k, p_v, p_ctx);

    // 4) O-proj + residual + LN + MLP1 + MLP2 (BM=128, BK=64)
    mega_oln_mlp<<<256, 512, MG_SMEM>>>(
        p_ctx, wo, w1, w2, bo, b1, b2, tex, ffg, ffb, p_x, out);
}

// round 14
// speedup vs baseline: 1.6375x; 1.0096x over previous
#include <cuda_runtime.h>
#include <cuda_bf16.h>
#include <cuda_fp16.h>
#include <cstdint>

#define F    256
#define VLEN 512
#define H    4
#define D    64
#define BB   8
#define NC   8

typedef __nv_bfloat16 bf16;
typedef __nv_bfloat162 bf162;

// ---------------- static device scratch ----------------
__device__ bf16   g_code2[(size_t)NC * VLEN * F];
__device__ bf16   g_tex2 [(size_t)BB * VLEN * F];
__device__ bf16   g_q[(size_t)BB * VLEN * F];
__device__ bf16   g_k[(size_t)NC * VLEN * F];
__device__ __half g_v[(size_t)NC * VLEN * F];
__device__ bf16   g_ctx[(size_t)BB * NC * VLEN * F];
__device__ float  g_x  [(size_t)BB * NC * VLEN * F];
__device__ bf16   g_w[6][F * F];

// ---------------- helpers ----------------
__device__ __forceinline__ unsigned h2_as_u32(__half2 h) {
    return *(unsigned*)&h;
}
__device__ __forceinline__ __half2 u32_as_h2(unsigned u) {
    return *(__half2*)&u;
}
__device__ __forceinline__ uint32_t smem_u32(const void* p) {
    return (uint32_t)__cvta_generic_to_shared(p);
}
__device__ __forceinline__ void mma_bf16(float (&d)[4], const unsigned (&a)[4],
                                         const unsigned b0, const unsigned b1) {
    asm volatile(
        "mma.sync.aligned.m16n8k16.row.col.f32.bf16.bf16.f32 "
        "{%0,%1,%2,%3}, {%4,%5,%6,%7}, {%8,%9}, {%0,%1,%2,%3};\n"
        : "+f"(d[0]), "+f"(d[1]), "+f"(d[2]), "+f"(d[3])
        : "r"(a[0]), "r"(a[1]), "r"(a[2]), "r"(a[3]), "r"(b0), "r"(b1));
}
__device__ __forceinline__ void mma_f16(float (&d)[4], const unsigned (&a)[4],
                                        const unsigned b0, const unsigned b1) {
    asm volatile(
        "mma.sync.aligned.m16n8k16.row.col.f32.f16.f16.f32 "
        "{%0,%1,%2,%3}, {%4,%5,%6,%7}, {%8,%9}, {%0,%1,%2,%3};\n"
        : "+f"(d[0]), "+f"(d[1]), "+f"(d[2]), "+f"(d[3])
        : "r"(a[0]), "r"(a[1]), "r"(a[2]), "r"(a[3]), "r"(b0), "r"(b1));
}
__device__ __forceinline__ void ldsm_x4(unsigned &r0, unsigned &r1,
                                        unsigned &r2, unsigned &r3, const void* p) {
    unsigned a = smem_u32(p);
    asm volatile("ldmatrix.sync.aligned.m8n8.x4.shared.b16 {%0,%1,%2,%3}, [%4];"
                 : "=r"(r0), "=r"(r1), "=r"(r2), "=r"(r3) : "r"(a));
}
__device__ __forceinline__ void ldsm_x4t(unsigned &r0, unsigned &r1,
                                         unsigned &r2, unsigned &r3, const void* p) {
    unsigned a = smem_u32(p);
    asm volatile("ldmatrix.sync.aligned.m8n8.x4.trans.shared.b16 {%0,%1,%2,%3}, [%4];"
                 : "=r"(r0), "=r"(r1), "=r"(r2), "=r"(r3) : "r"(a));
}
__device__ __forceinline__ void cp16(void* s, const void* g) {
    unsigned sa = smem_u32(s);
    asm volatile("cp.async.cg.shared.global [%0], [%1], 16;\n" :: "r"(sa), "l"(g));
}
__device__ __forceinline__ void cp_commit() { asm volatile("cp.async.commit_group;\n"); }
template<int N> __device__ __forceinline__ void cp_wait() {
    asm volatile("cp.async.wait_group %0;\n" :: "n"(N));
}

// ---------------- fused prep ----------------
__global__ __launch_bounds__(256) void prep_kernel(
    const float* __restrict__ code, const float* __restrict__ tex,
    const float* __restrict__ ln1g, const float* __restrict__ ln1b,
    const float* __restrict__ ln2g, const float* __restrict__ ln2b,
    const float* w0, const float* w1, const float* w2,
    const float* w3, const float* w4, const float* w5,
    bf16* __restrict__ wout)
{
    int bid = blockIdx.x;
    int t = threadIdx.x;
    if (bid < 1536) {
        int wi = bid >> 8;
        const float* s;
        switch (wi) {
            case 0: s = w0; break; case 1: s = w1; break; case 2: s = w2; break;
            case 3: s = w3; break; case 4: s = w4; break; default: s = w5; break;
        }
        int off = (bid & 255) * 256 + t;
        wout[(size_t)wi * F * F + off] = __float2bfloat16_rn(s[off]);
        return;
    }
    int row = bid - 1536;
    const float* x; const float* g; const float* b; bf16* y;
    if (row < NC * VLEN) { x = code; g = ln1g; b = ln1b; y = g_code2; }
    else { row -= NC * VLEN; x = tex; g = ln2g; b = ln2b; y = g_tex2; }

    __shared__ float sh[8];
    size_t base = (size_t)row * F;
    float v = x[base + t];

    float s = v;
    #pragma unroll
    for (int o = 16; o > 0; o >>= 1) s += __shfl_xor_sync(0xffffffffu, s, o);
    if ((t & 31) == 0) sh[t >> 5] = s;
    __syncthreads();
    float mean = (sh[0]+sh[1]+sh[2]+sh[3]+sh[4]+sh[5]+sh[6]+sh[7]) * (1.f / F);
    float d = v - mean;

    s = d * d;
    #pragma unroll
    for (int o = 16; o > 0; o >>= 1) s += __shfl_xor_sync(0xffffffffu, s, o);
    __syncthreads();
    if ((t & 31) == 0) sh[t >> 5] = s;
    __syncthreads();
    float var = (sh[0]+sh[1]+sh[2]+sh[3]+sh[4]+sh[5]+sh[6]+sh[7]) * (1.f / F);

    y[base + t] = __float2bfloat16_rn(d * rsqrtf(var + 1e-6f) * g[t] + b[t]);
}

// ======== wide-GEMM: BM=128, BN=256, 512 threads, BK=128, 2-stage ========
// Resident A: 128 rows x 528 B. Weight stage: 256 rows x 272 B (128 bf16 + pad).
#define RES_BYTES 67584               // 128 * 528
#define WB_STAGE  69632               // 256 * 272
#define QW_SMEM   (RES_BYTES + 2 * WB_STAGE)           // 206848
#define MG_SMEM   (RES_BYTES + 2 * WB_STAGE + 4096)    // 210944

// ---------------- QKV ----------------
__global__ __launch_bounds__(512, 1) void qkv_wide(
    const bf16* __restrict__ tex2, const bf16* __restrict__ code2,
    const bf16* __restrict__ wq, const bf16* __restrict__ wk, const bf16* __restrict__ wv,
    const float* __restrict__ bq, const float* __restrict__ bk, const float* __restrict__ bv,
    bf16* __restrict__ qo, bf16* __restrict__ ko, __half* __restrict__ vo)
{
    extern __shared__ char sm[];
    char* sRes = sm;
    char* sW   = sm + RES_BYTES;

    int z = blockIdx.y;
    const bf16* A = (z == 0) ? tex2 : code2;
    const bf16* W = (z == 0) ? wq : (z == 1) ? wk : wv;
    const float* bias = (z == 0) ? bq : (z == 1) ? bk : bv;

    int tid = threadIdx.x, wid = tid >> 5, lane = tid & 31;
    int g8 = lane >> 3, r8 = lane & 7, gr = lane >> 2, gc = lane & 3;
    int wm = wid >> 2, wn = wid & 3;
    int mb = wm * 32, nb = wn * 64;
    int m0 = blockIdx.x * 128;

    auto wload = [&](int ck) {
        char* sb = sW + (ck & 1) * WB_STAGE;
        int kc = ck * 128;
        #pragma unroll
        for (int j = 0; j < 8; j++) {
            int idx = tid + j * 512;
            int r = idx >> 4, cs = idx & 15;
            cp16(sb + r * 272 + cs * 16, W + (size_t)r * 256 + kc + cs * 8);
        }
        cp_commit();
    };

    {
        const bf16* Ab = A + (size_t)m0 * 256;
        #pragma unroll
        for (int j = 0; j < 8; j++) {
            int idx = tid + j * 512;
            int r = idx >> 5, cs = idx & 31;
            cp16(sRes + r * 528 + cs * 16, Ab + (size_t)r * 256 + cs * 8);
        }
        cp_commit();
    }
    wload(0);

    float acc[2][8][4] = {};

    for (int ck = 0; ck < 2; ck++) {
        cp_wait<0>(); __syncthreads();    // stage ck ready; prev stage reads done
        if (ck + 1 < 2) wload(ck + 1);    // overlaps compute below
        int ko_ = ck * 256;               // byte offset into A row (128 cols)
        const char* sb = sW + (ck & 1) * WB_STAGE;
        #pragma unroll
        for (int s = 0; s < 8; s++) {
            unsigned af[2][4];
            #pragma unroll
            for (int mt = 0; mt < 2; mt++) {
                int row = mb + mt * 16 + (g8 & 1) * 8 + r8;
                ldsm_x4(af[mt][0], af[mt][1], af[mt][2], af[mt][3],
                        sRes + row * 528 + ko_ + s * 32 + (g8 >> 1) * 16);
            }
            #pragma unroll
            for (int np = 0; np < 4; np++) {
                int row = nb + np * 16 + (g8 >> 1) * 8 + r8;
                unsigned b0, b1, b2, b3;
                ldsm_x4(b0, b1, b2, b3, sb + row * 272 + s * 32 + (g8 & 1) * 16);
                mma_bf16(acc[0][np * 2],     af[0], b0, b1);
                mma_bf16(acc[1][np * 2],     af[1], b0, b1);
                mma_bf16(acc[0][np * 2 + 1], af[0], b2, b3);
                mma_bf16(acc[1][np * 2 + 1], af[1], b2, b3);
            }
        }
    }

    #pragma unroll
    for (int mt = 0; mt < 2; mt++) {
        #pragma unroll
        for (int hf = 0; hf < 2; hf++) {
            int rg = m0 + mb + mt * 16 + gr + hf * 8;
            size_t rb = (size_t)rg * 256;
            #pragma unroll
            for (int nt = 0; nt < 8; nt++) {
                int c = nb + nt * 8 + 2 * gc;
                float v0 = acc[mt][nt][hf * 2]     + bias[c];
                float v1 = acc[mt][nt][hf * 2 + 1] + bias[c + 1];
                if (z == 2) {
                    *(__half2*)(vo + rb + c) = __floats2half2_rn(v0, v1);
                } else {
                    bf162 o = { __float2bfloat16_rn(v0), __float2bfloat16_rn(v1) };
                    bf16* C = (z == 0) ? qo : ko;
                    *(bf162*)(C + rb + c) = o;
                }
            }
        }
    }
}

// ---------------- mega: O-proj + residual + LN + MLP1 + MLP2 (BK=128, 2-stage) ----------------
__global__ __launch_bounds__(512, 1) void mega_oln_mlp(
    const bf16* __restrict__ ctx,
    const bf16* __restrict__ wo, const bf16* __restrict__ w1, const bf16* __restrict__ w2,
    const float* __restrict__ bo, const float* __restrict__ b1, const float* __restrict__ b2,
    const float* __restrict__ tex, const float* __restrict__ ffg, const float* __restrict__ ffb,
    float* __restrict__ X, float* __restrict__ out)
{
    extern __shared__ char sm[];
    char* sRes = sm;
    char* sW   = sm + RES_BYTES;
    float* sredS = (float*)(sm + RES_BYTES + 2 * WB_STAGE);   // [128][4]
    float* sredQ = sredS + 512;

    int tid = threadIdx.x, wid = tid >> 5, lane = tid & 31;
    int g8 = lane >> 3, r8 = lane & 7, gr = lane >> 2, gc = lane & 3;
    int wm = wid >> 2, wn = wid & 3;
    int mb = wm * 32, nb = wn * 64;
    int m0 = blockIdx.x * 128;

    const bf16* Ws[3] = { wo, w1, w2 };
    auto wload = [&](int ck) {
        const bf16* W = Ws[ck >> 1];
        char* sb = sW + (ck & 1) * WB_STAGE;
        int kc = (ck & 1) * 128;
        #pragma unroll
        for (int j = 0; j < 8; j++) {
            int idx = tid + j * 512;
            int r = idx >> 4, cs = idx & 15;
            cp16(sb + r * 272 + cs * 16, W + (size_t)r * 256 + kc + cs * 8);
        }
        cp_commit();
    };

    {
        const bf16* Ab = ctx + (size_t)m0 * 256;
        #pragma unroll
        for (int j = 0; j < 8; j++) {
            int idx = tid + j * 512;
            int r = idx >> 5, cs = idx & 31;
            cp16(sRes + r * 528 + cs * 16, Ab + (size_t)r * 256 + cs * 8);
        }
        cp_commit();
    }
    wload(0);

    float acc[2][8][4] = {};

    for (int ck = 0; ck < 6; ck++) {
        cp_wait<0>(); __syncthreads();    // stage ck ready; all prev-stage reads done
        if (ck + 1 < 6) wload(ck + 1);    // overlaps compute
        int ko_ = (ck & 1) * 256;
        const char* sb = sW + (ck & 1) * WB_STAGE;
        #pragma unroll
        for (int s = 0; s < 8; s++) {
            unsigned af[2][4];
            #pragma unroll
            for (int mt = 0; mt < 2; mt++) {
                int row = mb + mt * 16 + (g8 & 1) * 8 + r8;
                ldsm_x4(af[mt][0], af[mt][1], af[mt][2], af[mt][3],
                        sRes + row * 528 + ko_ + s * 32 + (g8 >> 1) * 16);
            }
            #pragma unroll
            for (int np = 0; np < 4; np++) {
                int row = nb + np * 16 + (g8 >> 1) * 8 + r8;
                unsigned b0, b1_, b2_, b3;
                ldsm_x4(b0, b1_, b2_, b3, sb + row * 272 + s * 32 + (g8 & 1) * 16);
                mma_bf16(acc[0][np * 2],     af[0], b0, b1_);
                mma_bf16(acc[1][np * 2],     af[1], b0, b1_);
                mma_bf16(acc[0][np * 2 + 1], af[0], b2_, b3);
                mma_bf16(acc[1][np * 2 + 1], af[1], b2_, b3);
            }
        }

        if (ck == 1) {
            // ---- epilogue A: x = acc + bo + tex; write x; LN -> yn into sRes ----
            float sS[2][2] = {}, sQ2[2][2] = {};
            #pragma unroll
            for (int mt = 0; mt < 2; mt++) {
                #pragma unroll
                for (int hf = 0; hf < 2; hf++) {
                    int rg = m0 + mb + mt * 16 + gr + hf * 8;
                    size_t rb = (size_t)rg * 256;
                    size_t tr = (size_t)(((rg >> 12) << 9) + (rg & 511)) * F;
                    #pragma unroll
                    for (int nt = 0; nt < 8; nt++) {
                        int c = nb + nt * 8 + 2 * gc;
                        float x0 = acc[mt][nt][hf * 2]     + bo[c]     + tex[tr + c];
                        float x1 = acc[mt][nt][hf * 2 + 1] + bo[c + 1] + tex[tr + c + 1];
                        acc[mt][nt][hf * 2] = x0; acc[mt][nt][hf * 2 + 1] = x1;
                        float2 o = { x0, x1 };
                        *(float2*)(X + rb + c) = o;
                        sS[mt][hf]  += x0 + x1;
                        sQ2[mt][hf] += x0 * x0 + x1 * x1;
                    }
                }
            }
            #pragma unroll
            for (int mt = 0; mt < 2; mt++)
                #pragma unroll
                for (int hf = 0; hf < 2; hf++) {
                    float a = sS[mt][hf], q = sQ2[mt][hf];
                    a += __shfl_xor_sync(0xffffffffu, a, 1);
                    a += __shfl_xor_sync(0xffffffffu, a, 2);
                    q += __shfl_xor_sync(0xffffffffu, q, 1);
                    q += __shfl_xor_sync(0xffffffffu, q, 2);
                    sS[mt][hf] = a; sQ2[mt][hf] = q;
                }
            if (gc == 0) {
                #pragma unroll
                for (int mt = 0; mt < 2; mt++)
                    #pragma unroll
                    for (int hf = 0; hf < 2; hf++) {
                        int rl = mb + mt * 16 + gr + hf * 8;
                        sredS[rl * 4 + wn] = sS[mt][hf];
                        sredQ[rl * 4 + wn] = sQ2[mt][hf];
                    }
            }
            __syncthreads();   // mma reads of sRes done; sred visible
            #pragma unroll
            for (int mt = 0; mt < 2; mt++) {
                #pragma unroll
                for (int hf = 0; hf < 2; hf++) {
                    int rl = mb + mt * 16 + gr + hf * 8;
                    const float* ps = sredS + rl * 4;
                    const float* pq = sredQ + rl * 4;
                    float S = ps[0] + ps[1] + ps[2] + ps[3];
                    float Q = pq[0] + pq[1] + pq[2] + pq[3];
                    float mu = S * (1.f / 256.f);
                    float var = Q * (1.f / 256.f) - mu * mu;
                    float rstd = rsqrtf(var + 1e-6f);
                    #pragma unroll
                    for (int nt = 0; nt < 8; nt++) {
                        int c = nb + nt * 8 + 2 * gc;
                        float y0 = (acc[mt][nt][hf * 2]     - mu) * rstd * ffg[c]     + ffb[c];
                        float y1 = (acc[mt][nt][hf * 2 + 1] - mu) * rstd * ffg[c + 1] + ffb[c + 1];
                        bf162 o = { __float2bfloat16_rn(y0), __float2bfloat16_rn(y1) };
                        *(bf162*)(sRes + rl * 528 + c * 2) = o;
                        acc[mt][nt][hf * 2] = 0.f; acc[mt][nt][hf * 2 + 1] = 0.f;
                    }
                }
            }
            // next loop-top barrier orders these sRes writes before reads
        } else if (ck == 3) {
            // ---- epilogue B: h1 = relu(acc + b1) -> sRes ----
            __syncthreads();   // all warps done reading yn from sRes
            #pragma unroll
            for (int mt = 0; mt < 2; mt++) {
                #pragma unroll
                for (int hf = 0; hf < 2; hf++) {
                    int rl = mb + mt * 16 + gr + hf * 8;
                    #pragma unroll
                    for (int nt = 0; nt < 8; nt++) {
                        int c = nb + nt * 8 + 2 * gc;
                        float h0 = fmaxf(acc[mt][nt][hf * 2]     + b1[c],     0.f);
                        float h1v = fmaxf(acc[mt][nt][hf * 2 + 1] + b1[c + 1], 0.f);
                        bf162 o = { __float2bfloat16_rn(h0), __float2bfloat16_rn(h1v) };
                        *(bf162*)(sRes + rl * 528 + c * 2) = o;
                        acc[mt][nt][hf * 2] = 0.f; acc[mt][nt][hf * 2 + 1] = 0.f;
                    }
                }
            }
            // next loop-top barrier orders these writes before reads
        }
    }

    // ---- epilogue C: out = acc + b2 + x ----
    #pragma unroll
    for (int mt = 0; mt < 2; mt++) {
        #pragma unroll
        for (int hf = 0; hf < 2; hf++) {
            int rg = m0 + mb + mt * 16 + gr + hf * 8;
            size_t rb = (size_t)rg * 256;
            #pragma unroll
            for (int nt = 0; nt < 8; nt++) {
                int c = nb + nt * 8 + 2 * gc;
                float o0 = acc[mt][nt][hf * 2]     + b2[c]     + X[rb + c];
                float o1 = acc[mt][nt][hf * 2 + 1] + b2[c + 1] + X[rb + c + 1];
                float2 o = { o0, o1 };
                *(float2*)(out + rb + c) = o;
            }
        }
    }
}

// ---------------- persistent fused attention (register-P) — unchanged ----------------
#define A_SMEM 232448

__global__ __launch_bounds__(512, 1) void attn_fused(
    const bf16* __restrict__ qg, const bf16* __restrict__ kg,
    const __half* __restrict__ vg, bf16* __restrict__ og)
{
    extern __shared__ char smc[];
    bf16* sQ = (bf16*)smc;
    bf16* sK = (bf16*)(smc + 9216);
    __half* sV = (__half*)(smc + 82944);
    char* sStage = smc + 156672;
    float* sred = (float*)(smc + 230400);

    int tid = threadIdx.x;
    int wid = tid >> 5, lane = tid & 31;
    int g8 = lane >> 3, r8 = lane & 7;
    int gr = lane >> 2, gc = lane & 3;

    int nh = blockIdx.y;
    int n = nh >> 2, h = nh & 3;
    int grp = blockIdx.x;

    const bf16*   K = kg + ((size_t)(n * VLEN)) * F + h * D;
    const __half* V = vg + ((size_t)(n * VLEN)) * F + h * D;

    int qr = tid >> 3, qc = (tid & 7) << 3;

    {
        int idx0 = grp * 16;
        int b0 = idx0 >> 3, q0 = idx0 & 7;
        const bf16* Q = qg + ((size_t)(b0 * VLEN + q0 * 64)) * F + h * D;
        cp16(sQ + qr * 72 + qc, Q + (size_t)qr * F + qc);
        #pragma unroll
        for (int j = 0; j < 8; j++) {
            int idx = tid + j * 512;
            int r = idx >> 3, c = (idx & 7) << 3;
            cp16(sK + r * 72 + c, K + (size_t)r * F + c);
            cp16(sV + r * 72 + c, V + (size_t)r * F + c);
        }
        cp_commit();
        cp_wait<0>();
        __syncthreads();
    }

    int wm = wid >> 3, wn = wid & 7;
    const float CEXP = 0.18033688f;

    int rr = wid * 4 + (lane >> 3);
    int rc = (lane & 7) * 8;

    for (int t = 0; t < 16; t++) {
        int idx = grp * 16 + t;
        int b = idx >> 3, qt = idx & 7;
        bf16* O = og + ((size_t)((b * NC + n) * VLEN + qt * 64)) * F + h * D;

        float acc[2][8][4] = {};
        #pragma unroll
        for (int s = 0; s < 4; s++) {
            unsigned af[2][4];
            #pragma unroll
            for (int mt = 0; mt < 2; mt++) {
                int row = wm * 32 + mt * 16 + (g8 & 1) * 8 + r8;
                ldsm_x4(af[mt][0], af[mt][1], af[mt][2], af[mt][3],
                        (const char*)sQ + row * 144 + s * 32 + (g8 >> 1) * 16);
            }
            #pragma unroll
            for (int np = 0; np < 4; np++) {
                int row = wn * 64 + np * 16 + (g8 >> 1) * 8 + r8;
                unsigned b0, b1, b2, b3;
                ldsm_x4(b0, b1, b2, b3,
                        (const char*)sK + row * 144 + s * 32 + (g8 & 1) * 16);
                mma_bf16(acc[0][np * 2],     af[0], b0, b1);
                mma_bf16(acc[1][np * 2],     af[1], b0, b1);
                mma_bf16(acc[0][np * 2 + 1], af[0], b2, b3);
                mma_bf16(acc[1][np * 2 + 1], af[1], b2, b3);
            }
        }

        unsigned ph[2][8][2];
        float rsum[2][2] = {};
        #pragma unroll
        for (int mt = 0; mt < 2; mt++)
            #pragma unroll
            for (int nt = 0; nt < 8; nt++) {
                __half2 p0 = h2exp2(__floats2half2_rn(acc[mt][nt][0] * CEXP,
                                                      acc[mt][nt][1] * CEXP));
                __half2 p1 = h2exp2(__floats2half2_rn(acc[mt][nt][2] * CEXP,
                                                      acc[mt][nt][3] * CEXP));
                ph[mt][nt][0] = h2_as_u32(p0);
                ph[mt][nt][1] = h2_as_u32(p1);
                float2 f0 = __half22float2(p0);
                float2 f1 = __half22float2(p1);
                rsum[mt][0] += f0.x + f0.y;
                rsum[mt][1] += f1.x + f1.y;
            }
        #pragma unroll
        for (int mt = 0; mt < 2; mt++)
            #pragma unroll
            for (int hf = 0; hf < 2; hf++) {
                float v = rsum[mt][hf];
                v += __shfl_xor_sync(0xffffffffu, v, 1);
                v += __shfl_xor_sync(0xffffffffu, v, 2);
                rsum[mt][hf] = v;
            }
        if (gc == 0) {
            #pragma unroll
            for (int mt = 0; mt < 2; mt++)
                #pragma unroll
                for (int hf = 0; hf < 2; hf++)
                    sred[(wm * 32 + mt * 16 + gr + hf * 8) * 8 + wn] = rsum[mt][hf];
        }

        float oacc[2][8][4] = {};
        #pragma unroll
        for (int s = 0; s < 4; s++) {
            unsigned a0[4] = { ph[0][2*s][0], ph[0][2*s][1],
                               ph[0][2*s+1][0], ph[0][2*s+1][1] };
            unsigned a1[4] = { ph[1][2*s][0], ph[1][2*s][1],
                               ph[1][2*s+1][0], ph[1][2*s+1][1] };
            #pragma unroll
            for (int nc = 0; nc < 4; nc++) {
                int row = wn * 64 + s * 16 + (g8 & 1) * 8 + r8;
                unsigned b0, b1, b2, b3;
                ldsm_x4t(b0, b1, b2, b3,
                         (const char*)sV + row * 144 + nc * 32 + (g8 >> 1) * 16);
                mma_f16(oacc[0][nc * 2],     a0, b0, b1);
                mma_f16(oacc[0][nc * 2 + 1], a0, b2, b3);
                mma_f16(oacc[1][nc * 2],     a1, b0, b1);
                mma_f16(oacc[1][nc * 2 + 1], a1, b2, b3);
            }
        }

        {
            char* st = sStage + wn * 9216;
            #pragma unroll
            for (int mt = 0; mt < 2; mt++)
                #pragma unroll
                for (int hf = 0; hf < 2; hf++) {
                    int row = wm * 32 + mt * 16 + gr + hf * 8;
                    #pragma unroll
                    for (int nt = 0; nt < 8; nt++) {
                        int c = nt * 8 + 2 * gc;
                        *(__half2*)(st + row * 144 + c * 2) =
                            __floats2half2_rn(oacc[mt][nt][hf * 2],
                                              oacc[mt][nt][hf * 2 + 1]);
                    }
                }
        }
        __syncthreads();

        if (t + 1 < 16) {
            int idx2 = grp * 16 + t + 1;
            int b2 = idx2 >> 3, q2 = idx2 & 7;
            const bf16* Qn = qg + ((size_t)(b2 * VLEN + q2 * 64)) * F + h * D;
            cp16(sQ + qr * 72 + qc, Qn + (size_t)qr * F + qc);
            cp_commit();
        }

        {
            const float* pr = sred + rr * 8;
            float inv = 1.f / (pr[0] + pr[1] + pr[2] + pr[3] +
                               pr[4] + pr[5] + pr[6] + pr[7]);
            float s0 = 0, s1 = 0, s2 = 0, s3 = 0, s4 = 0, s5 = 0, s6 = 0, s7 = 0;
            #pragma unroll
            for (int cp = 0; cp < 8; cp++) {
                uint4 v = *(const uint4*)(sStage + cp * 9216 + rr * 144 + rc * 2);
                float2 f0 = __half22float2(u32_as_h2(v.x));
                float2 f1 = __half22float2(u32_as_h2(v.y));
                float2 f2 = __half22float2(u32_as_h2(v.z));
                float2 f3 = __half22float2(u32_as_h2(v.w));
                s0 += f0.x; s1 += f0.y; s2 += f1.x; s3 += f1.y;
                s4 += f2.x; s5 += f2.y; s6 += f3.x; s7 += f3.y;
            }
            bf162 o0 = { __float2bfloat16_rn(s0 * inv), __float2bfloat16_rn(s1 * inv) };
            bf162 o1 = { __float2bfloat16_rn(s2 * inv), __float2bfloat16_rn(s3 * inv) };
            bf162 o2 = { __float2bfloat16_rn(s4 * inv), __float2bfloat16_rn(s5 * inv) };
            bf162 o3 = { __float2bfloat16_rn(s6 * inv), __float2bfloat16_rn(s7 * inv) };
            uint4 ov;
            ov.x = *(unsigned*)&o0; ov.y = *(unsigned*)&o1;
            ov.z = *(unsigned*)&o2; ov.w = *(unsigned*)&o3;
            *(uint4*)(O + (size_t)rr * F + rc) = ov;
        }

        cp_wait<0>();
        __syncthreads();
    }
}

// ---------------- launch ----------------
extern "C" void kernel_launch(void* const* d_in, const int* /*in_sizes*/, int /*n_in*/,
                              void* d_out, int /*out_size*/)
{
    const float* code = (const float*)d_in[0];
    const float* tex  = (const float*)d_in[1];
    const float* Wq   = (const float*)d_in[2];  const float* bq = (const float*)d_in[3];
    const float* Wk   = (const float*)d_in[4];  const float* bk = (const float*)d_in[5];
    const float* Wv   = (const float*)d_in[6];  const float* bv = (const float*)d_in[7];
    const float* Wo   = (const float*)d_in[8];  const float* bo = (const float*)d_in[9];
    const float* ln1g = (const float*)d_in[10]; const float* ln1b = (const float*)d_in[11];
    const float* ln2g = (const float*)d_in[12]; const float* ln2b = (const float*)d_in[13];
    const float* ffg  = (const float*)d_in[14]; const float* ffb  = (const float*)d_in[15];
    const float* W1   = (const float*)d_in[16]; const float* b1 = (const float*)d_in[17];
    const float* W2   = (const float*)d_in[18]; const float* b2 = (const float*)d_in[19];
    float* out = (float*)d_out;

    bf16 *p_code2, *p_tex2, *p_q, *p_k, *p_ctx, *p_w;
    __half *p_v;
    float *p_x;
    cudaGetSymbolAddress((void**)&p_code2, g_code2);
    cudaGetSymbolAddress((void**)&p_tex2,  g_tex2);
    cudaGetSymbolAddress((void**)&p_q,     g_q);
    cudaGetSymbolAddress((void**)&p_k,     g_k);
    cudaGetSymbolAddress((void**)&p_v,     g_v);
    cudaGetSymbolAddress((void**)&p_ctx,   g_ctx);
    cudaGetSymbolAddress((void**)&p_x,     g_x);
    cudaGetSymbolAddress((void**)&p_w,     g_w);
    bf16* wq = p_w;             bf16* wk = p_w + 1 * F * F; bf16* wv = p_w + 2 * F * F;
    bf16* wo = p_w + 3 * F * F; bf16* w1 = p_w + 4 * F * F; bf16* w2 = p_w + 5 * F * F;

    cudaFuncSetAttribute(qkv_wide,     cudaFuncAttributeMaxDynamicSharedMemorySize, QW_SMEM);
    cudaFuncSetAttribute(mega_oln_mlp, cudaFuncAttributeMaxDynamicSharedMemorySize, MG_SMEM);
    cudaFuncSetAttribute(attn_fused,   cudaFuncAttributeMaxDynamicSharedMemorySize, A_SMEM);

    // 1) fused prep
    prep_kernel<<<1536 + (NC + BB) * VLEN, 256>>>(
        code, tex, ln1g, ln1b, ln2g, ln2b,
        Wq, Wk, Wv, Wo, W1, W2, p_w);

    // 2) Q/K/V projections (BK=128, 2-stage)
    qkv_wide<<<dim3(32, 3), 512, QW_SMEM>>>(
        p_tex2, p_code2, wq, wk, wv, bq, bk, bv, p_q, p_k, p_v);

    // 3) persistent fused attention
    attn_fused<<<dim3(4, 32), 512, A_SMEM>>>(p_q, p_k, p_v, p_ctx);

    // 4) O-proj + residual + LN + MLP1 + MLP2 (BK=128, 2-stage)
    mega_oln_mlp<<<256, 512, MG_SMEM>>>(
        p_ctx, wo, w1, w2, bo, b1, b2, tex, ffg, ffb, p_x, out);
}